// round 1
// baseline (speedup 1.0000x reference)
#include <cuda_runtime.h>
#include <math.h>

#define N_NODES 50000
#define DIM     128
#define EDIM    32
#define HID     256
#define DEG     16
#define EPS     1e-5f

// Scratch (device globals: allocation-free rule)
__device__ float g_S[N_NODES * HID];      // node @ We1[0:128,:]
__device__ float g_R[N_NODES * HID];      // node @ We1[128:256,:] + be1
__device__ float g_Hagg[N_NODES * HID];   // sum over 16 edges of swish(pre)
__device__ float g_aggln[N_NODES * DIM];  // LN(agg)
__device__ float g_H[N_NODES * HID];      // node-MLP hidden (post swish)

__device__ __forceinline__ float swish_fast(float x) {
    // x * sigmoid(x); MUFU EX2 + MUFU RCP, ~1e-6 rel err
    float e = __expf(-x);
    return x * __fdividef(1.f, 1.f + e);
}

// ---------------------------------------------------------------------------
// K1: S = node @ We1[0:128,:]   ;   R = node @ We1[128:256,:] + be1
// Tiled GEMM M=64, N=256 (x2 passes), K=128 (tiles of 16). 256 threads.
// ---------------------------------------------------------------------------
__global__ __launch_bounds__(256) void k1_sr(
    const float* __restrict__ node, const float* __restrict__ We1,
    const float* __restrict__ be1)
{
    __shared__ float Xs[64][17];
    __shared__ float Ws[16][256];
    const int tid = threadIdx.x;
    const int ty = tid >> 4, tx = tid & 15;
    const int n0 = blockIdx.x * 64;

    for (int pass = 0; pass < 2; ++pass) {
        const float* Wbase = We1 + (pass ? (DIM * HID) : 0);
        float acc[4][16];
        #pragma unroll
        for (int r = 0; r < 4; ++r)
            #pragma unroll
            for (int i = 0; i < 16; ++i) acc[r][i] = 0.f;

        for (int kt = 0; kt < 8; ++kt) {
            __syncthreads();
            #pragma unroll
            for (int q = 0; q < 4; ++q) {
                int idx = tid + q * 256;
                int m = idx >> 4, k = idx & 15;
                int n = n0 + m;
                Xs[m][k] = (n < N_NODES) ? node[n * DIM + kt * 16 + k] : 0.f;
            }
            {
                int k  = tid >> 4;
                int c0 = (tid & 15) * 16;
                const float4* s4 = (const float4*)(Wbase + (kt * 16 + k) * HID + c0);
                float4* d4 = (float4*)&Ws[k][c0];
                d4[0] = s4[0]; d4[1] = s4[1]; d4[2] = s4[2]; d4[3] = s4[3];
            }
            __syncthreads();
            #pragma unroll
            for (int kk = 0; kk < 16; ++kk) {
                float a[4];
                #pragma unroll
                for (int r = 0; r < 4; ++r) a[r] = Xs[ty * 4 + r][kk];
                float bb[16];
                *(float4*)&bb[0]  = *(const float4*)&Ws[kk][tx * 16];
                *(float4*)&bb[4]  = *(const float4*)&Ws[kk][tx * 16 + 4];
                *(float4*)&bb[8]  = *(const float4*)&Ws[kk][tx * 16 + 8];
                *(float4*)&bb[12] = *(const float4*)&Ws[kk][tx * 16 + 12];
                #pragma unroll
                for (int r = 0; r < 4; ++r)
                    #pragma unroll
                    for (int i = 0; i < 16; ++i)
                        acc[r][i] = fmaf(a[r], bb[i], acc[r][i]);
            }
        }
        float bias[16];
        #pragma unroll
        for (int i = 0; i < 16; ++i) bias[i] = pass ? be1[tx * 16 + i] : 0.f;
        float* out = pass ? g_R : g_S;
        #pragma unroll
        for (int r = 0; r < 4; ++r) {
            int n = n0 + ty * 4 + r;
            if (n < N_NODES) {
                float tmp[16];
                #pragma unroll
                for (int i = 0; i < 16; ++i) tmp[i] = acc[r][i] + bias[i];
                float4* d = (float4*)(out + n * HID + tx * 16);
                d[0] = *(float4*)&tmp[0];  d[1] = *(float4*)&tmp[4];
                d[2] = *(float4*)&tmp[8];  d[3] = *(float4*)&tmp[12];
            }
        }
    }
}

// ---------------------------------------------------------------------------
// K2: per node n: Hagg[n] = sum_{e in 16 edges} swish(S[snd[e]] + R[n] + ef[e]@We1_edge)
// Block = 256 thr = 8 warps = 8 nodes. Warp owns one node; lane owns 8 cols.
// ---------------------------------------------------------------------------
__global__ __launch_bounds__(256) void k2_edge(
    const float* __restrict__ edge_feat, const int* __restrict__ senders,
    const float* __restrict__ We1)
{
    __shared__ float We1e[32][256];          // We1 rows 256..287  (32 KB)
    __shared__ float efs[8][16][32];         // per-warp edge features (16 KB)
    const int tid = threadIdx.x;

    #pragma unroll
    for (int q = 0; q < 8; ++q) {
        int i4 = tid + q * 256;              // float4 index over [32][64]
        int k = i4 >> 6, c = i4 & 63;
        ((float4*)&We1e[k][0])[c] = ((const float4*)(We1 + (256 + k) * HID))[c];
    }

    const int w = tid >> 5, lane = tid & 31;
    const int n  = blockIdx.x * 8 + w;       // grid = N/8 exactly
    const int e0 = n * DEG;
    {
        const float4* src = (const float4*)(edge_feat + e0 * EDIM);
        float4* dst = (float4*)&efs[w][0][0];
        #pragma unroll
        for (int q = 0; q < 4; ++q) dst[lane + q * 32] = src[lane + q * 32];
    }
    __syncthreads();

    const int cb = lane * 8;
    float rr[8];
    {
        const float4* r4 = (const float4*)(g_R + n * HID + cb);
        *(float4*)&rr[0] = r4[0]; *(float4*)&rr[4] = r4[1];
    }
    float hacc[8];
    #pragma unroll
    for (int i = 0; i < 8; ++i) hacc[i] = 0.f;

    for (int g = 0; g < 4; ++g) {
        int sidx[4];
        #pragma unroll
        for (int jj = 0; jj < 4; ++jj) sidx[jj] = senders[e0 + g * 4 + jj];

        float ep[4][8];
        #pragma unroll
        for (int jj = 0; jj < 4; ++jj)
            #pragma unroll
            for (int i = 0; i < 8; ++i) ep[jj][i] = 0.f;

        #pragma unroll
        for (int k = 0; k < 32; ++k) {
            float wv[8];
            *(float4*)&wv[0] = *(const float4*)&We1e[k][cb];
            *(float4*)&wv[4] = *(const float4*)&We1e[k][cb + 4];
            #pragma unroll
            for (int jj = 0; jj < 4; ++jj) {
                float f = efs[w][g * 4 + jj][k];
                #pragma unroll
                for (int i = 0; i < 8; ++i)
                    ep[jj][i] = fmaf(f, wv[i], ep[jj][i]);
            }
        }
        #pragma unroll
        for (int jj = 0; jj < 4; ++jj) {
            const float4* s4 = (const float4*)(g_S + sidx[jj] * HID + cb);
            float sv[8];
            *(float4*)&sv[0] = s4[0]; *(float4*)&sv[4] = s4[1];
            #pragma unroll
            for (int i = 0; i < 8; ++i) {
                float pre = sv[i] + rr[i] + ep[jj][i];
                hacc[i] += swish_fast(pre);
            }
        }
    }
    float4* o4 = (float4*)(g_Hagg + n * HID + cb);
    o4[0] = *(float4*)&hacc[0]; o4[1] = *(float4*)&hacc[4];
}

// ---------------------------------------------------------------------------
// K3: agg = LN( Hagg @ We2 / 16 + be2 ; g_msg,b_msg ) * mask   -> g_aggln
// GEMM M=64, N=128, K=256 (tiles 16) + row LN. 256 threads.
// ---------------------------------------------------------------------------
__global__ __launch_bounds__(256) void k3_aggln(
    const float* __restrict__ We2, const float* __restrict__ be2,
    const float* __restrict__ gmsg, const float* __restrict__ bmsg,
    const float* __restrict__ mask)
{
    __shared__ float sbuf[64 * 129];                      // 33 KB, unioned
    float (*Xs)[17]  = (float (*)[17])sbuf;
    float (*Ws)[128] = (float (*)[128])(sbuf + 64 * 17);
    float (*lnb)[129] = (float (*)[129])sbuf;

    const int tid = threadIdx.x;
    const int ty = tid >> 4, tx = tid & 15;
    const int n0 = blockIdx.x * 64;

    float acc[4][8];
    #pragma unroll
    for (int r = 0; r < 4; ++r)
        #pragma unroll
        for (int i = 0; i < 8; ++i) acc[r][i] = 0.f;

    for (int kt = 0; kt < 16; ++kt) {
        __syncthreads();
        #pragma unroll
        for (int q = 0; q < 4; ++q) {
            int idx = tid + q * 256;
            int m = idx >> 4, k = idx & 15;
            int n = n0 + m;
            Xs[m][k] = (n < N_NODES) ? g_Hagg[n * HID + kt * 16 + k] : 0.f;
        }
        #pragma unroll
        for (int q = 0; q < 2; ++q) {
            int i4 = tid + q * 256;                       // float4 idx over [16][32]
            int k = i4 >> 5, c = i4 & 31;
            ((float4*)&Ws[k][0])[c] = ((const float4*)(We2 + (kt * 16 + k) * DIM))[c];
        }
        __syncthreads();
        #pragma unroll
        for (int kk = 0; kk < 16; ++kk) {
            float a[4];
            #pragma unroll
            for (int r = 0; r < 4; ++r) a[r] = Xs[ty * 4 + r][kk];
            float bb[8];
            *(float4*)&bb[0] = *(const float4*)&Ws[kk][tx * 8];
            *(float4*)&bb[4] = *(const float4*)&Ws[kk][tx * 8 + 4];
            #pragma unroll
            for (int r = 0; r < 4; ++r)
                #pragma unroll
                for (int i = 0; i < 8; ++i)
                    acc[r][i] = fmaf(a[r], bb[i], acc[r][i]);
        }
    }
    __syncthreads();
    #pragma unroll
    for (int r = 0; r < 4; ++r)
        #pragma unroll
        for (int i = 0; i < 8; ++i) {
            int j = tx * 8 + i;
            lnb[ty * 4 + r][j] = acc[r][i] * (1.f / DEG) + be2[j];
        }
    __syncthreads();

    const int wp = tid >> 5, lane = tid & 31;
    for (int rw = 0; rw < 8; ++rw) {
        int m = wp * 8 + rw;
        int n = n0 + m;
        float x[4];
        #pragma unroll
        for (int q = 0; q < 4; ++q) x[q] = lnb[m][lane + 32 * q];
        float s  = x[0] + x[1] + x[2] + x[3];
        float ss = x[0]*x[0] + x[1]*x[1] + x[2]*x[2] + x[3]*x[3];
        #pragma unroll
        for (int o = 16; o > 0; o >>= 1) {
            s  += __shfl_xor_sync(0xffffffffu, s,  o);
            ss += __shfl_xor_sync(0xffffffffu, ss, o);
        }
        float mean = s * (1.f / DIM);
        float var  = ss * (1.f / DIM) - mean * mean;
        float inv  = rsqrtf(var + EPS);
        if (n < N_NODES) {
            float mk = mask[n];
            #pragma unroll
            for (int q = 0; q < 4; ++q) {
                int j = lane + 32 * q;
                g_aggln[n * DIM + j] = ((x[q] - mean) * inv * gmsg[j] + bmsg[j]) * mk;
            }
        }
    }
}

// ---------------------------------------------------------------------------
// K4a: H = swish( [node | aggln] @ Wn1 + bn1 )   (M=64, N=256, K=256)
// ---------------------------------------------------------------------------
__global__ __launch_bounds__(256) void k4a_hidden(
    const float* __restrict__ node, const float* __restrict__ Wn1,
    const float* __restrict__ bn1)
{
    __shared__ float Xs[64][17];
    __shared__ float Ws[16][256];
    const int tid = threadIdx.x;
    const int ty = tid >> 4, tx = tid & 15;
    const int n0 = blockIdx.x * 64;

    float acc[4][16];
    #pragma unroll
    for (int r = 0; r < 4; ++r)
        #pragma unroll
        for (int i = 0; i < 16; ++i) acc[r][i] = 0.f;

    for (int kt = 0; kt < 16; ++kt) {
        __syncthreads();
        #pragma unroll
        for (int q = 0; q < 4; ++q) {
            int idx = tid + q * 256;
            int m = idx >> 4, k = idx & 15;
            int n = n0 + m;
            float v = 0.f;
            if (n < N_NODES) {
                v = (kt < 8) ? node[n * DIM + kt * 16 + k]
                             : g_aggln[n * DIM + (kt - 8) * 16 + k];
            }
            Xs[m][k] = v;
        }
        {
            int k  = tid >> 4;
            int c0 = (tid & 15) * 16;
            const float4* s4 = (const float4*)(Wn1 + (kt * 16 + k) * HID + c0);
            float4* d4 = (float4*)&Ws[k][c0];
            d4[0] = s4[0]; d4[1] = s4[1]; d4[2] = s4[2]; d4[3] = s4[3];
        }
        __syncthreads();
        #pragma unroll
        for (int kk = 0; kk < 16; ++kk) {
            float a[4];
            #pragma unroll
            for (int r = 0; r < 4; ++r) a[r] = Xs[ty * 4 + r][kk];
            float bb[16];
            *(float4*)&bb[0]  = *(const float4*)&Ws[kk][tx * 16];
            *(float4*)&bb[4]  = *(const float4*)&Ws[kk][tx * 16 + 4];
            *(float4*)&bb[8]  = *(const float4*)&Ws[kk][tx * 16 + 8];
            *(float4*)&bb[12] = *(const float4*)&Ws[kk][tx * 16 + 12];
            #pragma unroll
            for (int r = 0; r < 4; ++r)
                #pragma unroll
                for (int i = 0; i < 16; ++i)
                    acc[r][i] = fmaf(a[r], bb[i], acc[r][i]);
        }
    }
    #pragma unroll
    for (int r = 0; r < 4; ++r) {
        int n = n0 + ty * 4 + r;
        if (n < N_NODES) {
            float tmp[16];
            #pragma unroll
            for (int i = 0; i < 16; ++i) {
                float pre = acc[r][i] + bn1[tx * 16 + i];
                tmp[i] = swish_fast(pre);
            }
            float4* d = (float4*)(g_H + n * HID + tx * 16);
            d[0] = *(float4*)&tmp[0];  d[1] = *(float4*)&tmp[4];
            d[2] = *(float4*)&tmp[8];  d[3] = *(float4*)&tmp[12];
        }
    }
}

// ---------------------------------------------------------------------------
// K4b: out = LN( H @ Wn2 + bn2 + node ; g_node,b_node ) * mask
// ---------------------------------------------------------------------------
__global__ __launch_bounds__(256) void k4b_out(
    const float* __restrict__ node, const float* __restrict__ Wn2,
    const float* __restrict__ bn2, const float* __restrict__ gnode,
    const float* __restrict__ bnode, const float* __restrict__ mask,
    float* __restrict__ out)
{
    __shared__ float sbuf[64 * 129];
    float (*Xs)[17]  = (float (*)[17])sbuf;
    float (*Ws)[128] = (float (*)[128])(sbuf + 64 * 17);
    float (*lnb)[129] = (float (*)[129])sbuf;

    const int tid = threadIdx.x;
    const int ty = tid >> 4, tx = tid & 15;
    const int n0 = blockIdx.x * 64;

    float acc[4][8];
    #pragma unroll
    for (int r = 0; r < 4; ++r)
        #pragma unroll
        for (int i = 0; i < 8; ++i) acc[r][i] = 0.f;

    for (int kt = 0; kt < 16; ++kt) {
        __syncthreads();
        #pragma unroll
        for (int q = 0; q < 4; ++q) {
            int idx = tid + q * 256;
            int m = idx >> 4, k = idx & 15;
            int n = n0 + m;
            Xs[m][k] = (n < N_NODES) ? g_H[n * HID + kt * 16 + k] : 0.f;
        }
        #pragma unroll
        for (int q = 0; q < 2; ++q) {
            int i4 = tid + q * 256;
            int k = i4 >> 5, c = i4 & 31;
            ((float4*)&Ws[k][0])[c] = ((const float4*)(Wn2 + (kt * 16 + k) * DIM))[c];
        }
        __syncthreads();
        #pragma unroll
        for (int kk = 0; kk < 16; ++kk) {
            float a[4];
            #pragma unroll
            for (int r = 0; r < 4; ++r) a[r] = Xs[ty * 4 + r][kk];
            float bb[8];
            *(float4*)&bb[0] = *(const float4*)&Ws[kk][tx * 8];
            *(float4*)&bb[4] = *(const float4*)&Ws[kk][tx * 8 + 4];
            #pragma unroll
            for (int r = 0; r < 4; ++r)
                #pragma unroll
                for (int i = 0; i < 8; ++i)
                    acc[r][i] = fmaf(a[r], bb[i], acc[r][i]);
        }
    }
    __syncthreads();
    #pragma unroll
    for (int r = 0; r < 4; ++r) {
        int m = ty * 4 + r;
        int n = n0 + m;
        #pragma unroll
        for (int i = 0; i < 8; ++i) {
            int j = tx * 8 + i;
            float res = (n < N_NODES) ? node[n * DIM + j] : 0.f;
            lnb[m][j] = acc[r][i] + bn2[j] + res;
        }
    }
    __syncthreads();

    const int wp = tid >> 5, lane = tid & 31;
    for (int rw = 0; rw < 8; ++rw) {
        int m = wp * 8 + rw;
        int n = n0 + m;
        float x[4];
        #pragma unroll
        for (int q = 0; q < 4; ++q) x[q] = lnb[m][lane + 32 * q];
        float s  = x[0] + x[1] + x[2] + x[3];
        float ss = x[0]*x[0] + x[1]*x[1] + x[2]*x[2] + x[3]*x[3];
        #pragma unroll
        for (int o = 16; o > 0; o >>= 1) {
            s  += __shfl_xor_sync(0xffffffffu, s,  o);
            ss += __shfl_xor_sync(0xffffffffu, ss, o);
        }
        float mean = s * (1.f / DIM);
        float var  = ss * (1.f / DIM) - mean * mean;
        float inv  = rsqrtf(var + EPS);
        if (n < N_NODES) {
            float mk = mask[n];
            #pragma unroll
            for (int q = 0; q < 4; ++q) {
                int j = lane + 32 * q;
                out[n * DIM + j] = ((x[q] - mean) * inv * gnode[j] + bnode[j]) * mk;
            }
        }
    }
}

// ---------------------------------------------------------------------------
extern "C" void kernel_launch(void* const* d_in, const int* in_sizes, int n_in,
                              void* d_out, int out_size)
{
    const float* node      = (const float*)d_in[0];
    const float* edge_feat = (const float*)d_in[1];
    const float* mask      = (const float*)d_in[2];
    const float* We1       = (const float*)d_in[3];
    const float* be1       = (const float*)d_in[4];
    const float* We2       = (const float*)d_in[5];
    const float* be2       = (const float*)d_in[6];
    const float* gmsg      = (const float*)d_in[7];
    const float* bmsg      = (const float*)d_in[8];
    const float* Wn1       = (const float*)d_in[9];
    const float* bn1       = (const float*)d_in[10];
    const float* Wn2       = (const float*)d_in[11];
    const float* bn2       = (const float*)d_in[12];
    const float* gnode     = (const float*)d_in[13];
    const float* bnode     = (const float*)d_in[14];
    const int*   senders   = (const int*)d_in[15];
    // d_in[16] = receivers: structurally repeat(arange(N), 16) — exploited implicitly
    float* out = (float*)d_out;

    const int gb = (N_NODES + 63) / 64;     // 782

    k1_sr     <<<gb, 256>>>(node, We1, be1);
    k2_edge   <<<N_NODES / 8, 256>>>(edge_feat, senders, We1);
    k3_aggln  <<<gb, 256>>>(We2, be2, gmsg, bmsg, mask);
    k4a_hidden<<<gb, 256>>>(node, Wn1, bn1);
    k4b_out   <<<gb, 256>>>(node, Wn2, bn2, gnode, bnode, mask, out);
}

// round 2
// speedup vs baseline: 2.5656x; 2.5656x over previous
#include <cuda_runtime.h>
#include <cuda_bf16.h>
#include <math.h>

#define N_NODES 50000
#define E_EDGES 800000
#define DIM     128
#define EDIM    32
#define HID     256
#define DEG     16
#define EPS     1e-5f

// ---------------- scratch (device globals; allocation-free rule) ------------
__device__ float        g_S[N_NODES * HID];        // node @ We1[0:128,:]
__device__ float        g_R[N_NODES * HID];        // node @ We1[128:256,:] + be1
__device__ unsigned int g_EP[E_EDGES * (HID / 2)]; // edge_feat @ We1[256:288,:], bf16x2
__device__ float        g_Hagg[N_NODES * HID];     // sum_e swish(pre)
__device__ float        g_aggln[N_NODES * DIM];    // LN(agg)
__device__ float        g_H[N_NODES * HID];        // node-MLP hidden (post swish)

__device__ __forceinline__ float swish_fast(float x) {
    float e = __expf(-x);
    return x * __fdividef(1.f, 1.f + e);
}

// ---------------- mma.m16n8k16 bf16 (fp32 accumulate) -----------------------
__device__ __forceinline__ void mma_bf16(float (&c)[4],
                                         unsigned a0, unsigned a1, unsigned a2, unsigned a3,
                                         unsigned b0, unsigned b1) {
    asm volatile(
        "mma.sync.aligned.m16n8k16.row.col.f32.bf16.bf16.f32 "
        "{%0,%1,%2,%3}, {%4,%5,%6,%7}, {%8,%9}, {%0,%1,%2,%3};"
        : "+f"(c[0]), "+f"(c[1]), "+f"(c[2]), "+f"(c[3])
        : "r"(a0), "r"(a1), "r"(a2), "r"(a3), "r"(b0), "r"(b1));
}

// Tile geometry: CTA 128x128, K-chunk 32, smem stride 40 bf16 (20 words)
#define KPAD 40
#define TILE_BYTES (128 * KPAD * 2)   // 10240 per tile

// Load+split A tile: rows [m0,m0+128) x cols [k0,k0+32), row-major src (ld)
__device__ __forceinline__ void load_split_A(
    const float* __restrict__ src, int ld, int m0, int mmax, int k0,
    __nv_bfloat16* Ah, __nv_bfloat16* Al, int tid)
{
    #pragma unroll
    for (int q = 0; q < 4; ++q) {
        int idx4 = tid + q * 256;
        int r   = idx4 >> 3;
        int kc4 = (idx4 & 7) * 4;
        float4 v = make_float4(0.f, 0.f, 0.f, 0.f);
        int grow = m0 + r;
        if (grow < mmax)
            v = *(const float4*)(src + (long long)grow * ld + k0 + kc4);
        float vv[4] = {v.x, v.y, v.z, v.w};
        #pragma unroll
        for (int j = 0; j < 4; ++j) {
            __nv_bfloat16 h = __float2bfloat16_rn(vv[j]);
            __nv_bfloat16 l = __float2bfloat16_rn(vv[j] - __bfloat162float(h));
            Ah[r * KPAD + kc4 + j] = h;
            Al[r * KPAD + kc4 + j] = l;
        }
    }
}

// Load+split+transpose B tile: W row-major [K][ldw]; tile k0..+32 x n0..+128
// stored as Bs[n][k]
__device__ __forceinline__ void load_split_B(
    const float* __restrict__ W, int ldw, int k0, int n0,
    __nv_bfloat16* Bh, __nv_bfloat16* Bl, int tid)
{
    #pragma unroll
    for (int q = 0; q < 4; ++q) {
        int idx4 = tid + q * 256;
        int k   = idx4 >> 5;          // 0..31
        int nc4 = (idx4 & 31) * 4;    // 0..124
        float4 v = *(const float4*)(W + (k0 + k) * ldw + n0 + nc4);
        float vv[4] = {v.x, v.y, v.z, v.w};
        #pragma unroll
        for (int j = 0; j < 4; ++j) {
            __nv_bfloat16 h = __float2bfloat16_rn(vv[j]);
            __nv_bfloat16 l = __float2bfloat16_rn(vv[j] - __bfloat162float(h));
            Bh[(nc4 + j) * KPAD + k] = h;
            Bl[(nc4 + j) * KPAD + k] = l;
        }
    }
}

// One K=32 chunk of 3-term split mma. Warp tile 32x64: wm in 0..3, wn in 0..1.
__device__ __forceinline__ void mma_chunk(
    const unsigned* Ah32, const unsigned* Al32,
    const unsigned* Bh32, const unsigned* Bl32,
    float (&C)[2][8][4], int wm, int wn, int lane)
{
    const int gr = lane >> 2, tc = lane & 3;
    #pragma unroll
    for (int ks2 = 0; ks2 < 16; ks2 += 8) {       // k-step 0 and 16 (in half-words)
        unsigned ah[2][4], al[2][4];
        #pragma unroll
        for (int mf = 0; mf < 2; ++mf) {
            int r = wm * 32 + mf * 16 + gr;
            const unsigned* p  = Ah32 + r * 20 + ks2 + tc;
            ah[mf][0] = p[0];  ah[mf][1] = p[160];  ah[mf][2] = p[4];  ah[mf][3] = p[164];
            const unsigned* p2 = Al32 + r * 20 + ks2 + tc;
            al[mf][0] = p2[0]; al[mf][1] = p2[160]; al[mf][2] = p2[4]; al[mf][3] = p2[164];
        }
        #pragma unroll
        for (int nf = 0; nf < 8; ++nf) {
            int n = wn * 64 + nf * 8 + gr;
            const unsigned* pb = Bh32 + n * 20 + ks2 + tc;
            unsigned bh0 = pb[0], bh1 = pb[4];
            const unsigned* pl = Bl32 + n * 20 + ks2 + tc;
            unsigned bl0 = pl[0], bl1 = pl[4];
            #pragma unroll
            for (int mf = 0; mf < 2; ++mf) {
                mma_bf16(C[mf][nf], ah[mf][0], ah[mf][1], ah[mf][2], ah[mf][3], bh0, bh1);
                mma_bf16(C[mf][nf], ah[mf][0], ah[mf][1], ah[mf][2], ah[mf][3], bl0, bl1);
                mma_bf16(C[mf][nf], al[mf][0], al[mf][1], al[mf][2], al[mf][3], bh0, bh1);
            }
        }
    }
}

// Fused LayerNorm epilogue over CTA tile 128 rows x 128 cols (NT == DIM).
// val = C*scale + bias[col] (+ resid[row][col]); out = LN(val)*mask
__device__ __forceinline__ void ln_epilogue(
    float (&C)[2][8][4], float* lnbuf, int m0, int wm, int wn, int w, int lane,
    float scale, const float* __restrict__ bias,
    const float* __restrict__ resid,
    const float* __restrict__ gamma, const float* __restrict__ beta,
    const float* __restrict__ mask, float* __restrict__ out)
{
    const int gr = lane >> 2, tc = lane & 3;
    #pragma unroll
    for (int half = 0; half < 2; ++half) {
        __syncthreads();
        if ((wm >> 1) == half) {
            #pragma unroll
            for (int mf = 0; mf < 2; ++mf) {
                int lr   = (wm & 1) * 32 + mf * 16 + gr;      // 0..63
                int grow = m0 + half * 64 + lr;
                #pragma unroll
                for (int nf = 0; nf < 8; ++nf) {
                    int col = wn * 64 + nf * 8 + 2 * tc;
                    float r0 = 0.f, r1 = 0.f, r2 = 0.f, r3 = 0.f;
                    if (resid) {
                        if (grow < N_NODES) {
                            r0 = resid[grow * DIM + col];
                            r1 = resid[grow * DIM + col + 1];
                        }
                        if (grow + 8 < N_NODES) {
                            r2 = resid[(grow + 8) * DIM + col];
                            r3 = resid[(grow + 8) * DIM + col + 1];
                        }
                    }
                    float b0 = bias[col], b1 = bias[col + 1];
                    lnbuf[lr * 132 + col]           = C[mf][nf][0] * scale + b0 + r0;
                    lnbuf[lr * 132 + col + 1]       = C[mf][nf][1] * scale + b1 + r1;
                    lnbuf[(lr + 8) * 132 + col]     = C[mf][nf][2] * scale + b0 + r2;
                    lnbuf[(lr + 8) * 132 + col + 1] = C[mf][nf][3] * scale + b1 + r3;
                }
            }
        }
        __syncthreads();
        #pragma unroll
        for (int rw = 0; rw < 8; ++rw) {
            int m    = w * 8 + rw;
            int grow = m0 + half * 64 + m;
            float x[4];
            #pragma unroll
            for (int q = 0; q < 4; ++q) x[q] = lnbuf[m * 132 + lane + 32 * q];
            float s  = x[0] + x[1] + x[2] + x[3];
            float ss = x[0]*x[0] + x[1]*x[1] + x[2]*x[2] + x[3]*x[3];
            #pragma unroll
            for (int o = 16; o > 0; o >>= 1) {
                s  += __shfl_xor_sync(0xffffffffu, s,  o);
                ss += __shfl_xor_sync(0xffffffffu, ss, o);
            }
            float mean = s * (1.f / DIM);
            float var  = ss * (1.f / DIM) - mean * mean;
            float inv  = rsqrtf(var + EPS);
            if (grow < N_NODES) {
                float mk = mask[grow];
                #pragma unroll
                for (int q = 0; q < 4; ++q) {
                    int j = lane + 32 * q;
                    out[grow * DIM + j] = ((x[q] - mean) * inv * gamma[j] + beta[j]) * mk;
                }
            }
        }
    }
}

#define GEMM_PROLOGUE()                                                        \
    __shared__ __align__(16) unsigned char smraw[4 * TILE_BYTES];              \
    __nv_bfloat16* Ah = (__nv_bfloat16*)smraw;                                 \
    __nv_bfloat16* Al = Ah + 128 * KPAD;                                       \
    __nv_bfloat16* Bh = Al + 128 * KPAD;                                       \
    __nv_bfloat16* Bl = Bh + 128 * KPAD;                                       \
    const unsigned* Ah32 = (const unsigned*)Ah;                                \
    const unsigned* Al32 = (const unsigned*)Al;                                \
    const unsigned* Bh32 = (const unsigned*)Bh;                                \
    const unsigned* Bl32 = (const unsigned*)Bl;                                \
    const int tid = threadIdx.x;                                               \
    const int w = tid >> 5, lane = tid & 31;                                   \
    const int wm = w & 3, wn = w >> 2;                                         \
    const int gr = lane >> 2, tc = lane & 3;                                   \
    float C[2][8][4];                                                          \
    _Pragma("unroll") for (int mf = 0; mf < 2; ++mf)                           \
        _Pragma("unroll") for (int nf = 0; nf < 8; ++nf)                       \
            _Pragma("unroll") for (int i = 0; i < 4; ++i) C[mf][nf][i] = 0.f;

// ---------------------------------------------------------------------------
// K1: S = node@We1[0:128,:], R = node@We1[128:256,:] + be1
// grid (391, 4): y>>1 selects S/R, y&1 selects column half
// ---------------------------------------------------------------------------
__global__ __launch_bounds__(256) void k1_sr(
    const float* __restrict__ node, const float* __restrict__ We1,
    const float* __restrict__ be1)
{
    GEMM_PROLOGUE();
    const int m0 = blockIdx.x * 128;
    const int which = blockIdx.y >> 1;
    const int n0 = (blockIdx.y & 1) * 128;
    const float* W = We1 + which * DIM * HID;

    for (int kc = 0; kc < 4; ++kc) {
        __syncthreads();
        load_split_A(node, DIM, m0, N_NODES, kc * 32, Ah, Al, tid);
        load_split_B(W, HID, kc * 32, n0, Bh, Bl, tid);
        __syncthreads();
        mma_chunk(Ah32, Al32, Bh32, Bl32, C, wm, wn, lane);
    }
    float* out = which ? g_R : g_S;
    #pragma unroll
    for (int mf = 0; mf < 2; ++mf) {
        int row = m0 + wm * 32 + mf * 16 + gr;
        #pragma unroll
        for (int nf = 0; nf < 8; ++nf) {
            int col = n0 + wn * 64 + nf * 8 + 2 * tc;
            float b0 = which ? be1[col] : 0.f;
            float b1 = which ? be1[col + 1] : 0.f;
            if (row < N_NODES)
                *(float2*)(out + row * HID + col) =
                    make_float2(C[mf][nf][0] + b0, C[mf][nf][1] + b1);
            if (row + 8 < N_NODES)
                *(float2*)(out + (row + 8) * HID + col) =
                    make_float2(C[mf][nf][2] + b0, C[mf][nf][3] + b1);
        }
    }
}

// ---------------------------------------------------------------------------
// K_EP: EP = edge_feat @ We1[256:288,:]  (E x 256), stored bf16x2
// grid (6250, 2). K = 32 (single chunk).
// ---------------------------------------------------------------------------
__global__ __launch_bounds__(256) void k_ep(
    const float* __restrict__ edge_feat, const float* __restrict__ We1)
{
    GEMM_PROLOGUE();
    const int m0 = blockIdx.x * 128;
    const int n0 = blockIdx.y * 128;
    const float* W = We1 + 2 * DIM * HID;   // edge rows

    load_split_A(edge_feat, EDIM, m0, E_EDGES, 0, Ah, Al, tid);
    load_split_B(W, HID, 0, n0, Bh, Bl, tid);
    __syncthreads();
    mma_chunk(Ah32, Al32, Bh32, Bl32, C, wm, wn, lane);

    #pragma unroll
    for (int mf = 0; mf < 2; ++mf) {
        int row = m0 + wm * 32 + mf * 16 + gr;
        #pragma unroll
        for (int nf = 0; nf < 8; ++nf) {
            int col = n0 + wn * 64 + nf * 8 + 2 * tc;
            if (row < E_EDGES) {
                __nv_bfloat162 t = __floats2bfloat162_rn(C[mf][nf][0], C[mf][nf][1]);
                g_EP[row * 128 + (col >> 1)] = *(unsigned*)&t;
            }
            if (row + 8 < E_EDGES) {
                __nv_bfloat162 t = __floats2bfloat162_rn(C[mf][nf][2], C[mf][nf][3]);
                g_EP[(row + 8) * 128 + (col >> 1)] = *(unsigned*)&t;
            }
        }
    }
}

// ---------------------------------------------------------------------------
// K2: Hagg[n] = sum over 16 edges of swish(S[snd] + R[n] + EP[e])
// warp per node, lane owns 8 cols
// ---------------------------------------------------------------------------
__global__ __launch_bounds__(256) void k2_edge(const int* __restrict__ senders)
{
    const int tid = threadIdx.x, w = tid >> 5, lane = tid & 31;
    const int n = blockIdx.x * 8 + w;
    const int e0 = n * DEG;
    const int cb = lane * 8;

    float rr[8];
    {
        const float4* r4 = (const float4*)(g_R + n * HID + cb);
        *(float4*)&rr[0] = r4[0]; *(float4*)&rr[4] = r4[1];
    }
    float hacc[8];
    #pragma unroll
    for (int i = 0; i < 8; ++i) hacc[i] = 0.f;

    int sidx[16];
    #pragma unroll
    for (int e = 0; e < 16; ++e) sidx[e] = senders[e0 + e];

    #pragma unroll
    for (int e = 0; e < 16; ++e) {
        const float4* s4 = (const float4*)(g_S + sidx[e] * HID + cb);
        float4 s0 = s4[0], s1 = s4[1];
        uint4 ep = *(const uint4*)(g_EP + (e0 + e) * 128 + lane * 4);
        float sv[8] = {s0.x, s0.y, s0.z, s0.w, s1.x, s1.y, s1.z, s1.w};
        unsigned epu[4] = {ep.x, ep.y, ep.z, ep.w};
        #pragma unroll
        for (int j = 0; j < 4; ++j) {
            __nv_bfloat162 b = *(__nv_bfloat162*)&epu[j];
            float e0f = __bfloat162float(b.x);
            float e1f = __bfloat162float(b.y);
            float p0 = sv[2 * j]     + rr[2 * j]     + e0f;
            float p1 = sv[2 * j + 1] + rr[2 * j + 1] + e1f;
            hacc[2 * j]     += swish_fast(p0);
            hacc[2 * j + 1] += swish_fast(p1);
        }
    }
    float4* o4 = (float4*)(g_Hagg + n * HID + cb);
    o4[0] = *(float4*)&hacc[0]; o4[1] = *(float4*)&hacc[4];
}

// ---------------------------------------------------------------------------
// K3: aggln = LN(Hagg @ We2 / 16 + be2; gmsg,bmsg) * mask
// ---------------------------------------------------------------------------
__global__ __launch_bounds__(256) void k3_aggln(
    const float* __restrict__ We2, const float* __restrict__ be2,
    const float* __restrict__ gmsg, const float* __restrict__ bmsg,
    const float* __restrict__ mask)
{
    GEMM_PROLOGUE();
    const int m0 = blockIdx.x * 128;
    for (int kc = 0; kc < 8; ++kc) {
        __syncthreads();
        load_split_A(g_Hagg, HID, m0, N_NODES, kc * 32, Ah, Al, tid);
        load_split_B(We2, DIM, kc * 32, 0, Bh, Bl, tid);
        __syncthreads();
        mma_chunk(Ah32, Al32, Bh32, Bl32, C, wm, wn, lane);
    }
    ln_epilogue(C, (float*)smraw, m0, wm, wn, w, lane,
                1.f / DEG, be2, nullptr, gmsg, bmsg, mask, g_aggln);
}

// ---------------------------------------------------------------------------
// K4a: H = swish([node | aggln] @ Wn1 + bn1)
// grid (391, 2)
// ---------------------------------------------------------------------------
__global__ __launch_bounds__(256) void k4a_hidden(
    const float* __restrict__ node, const float* __restrict__ Wn1,
    const float* __restrict__ bn1)
{
    GEMM_PROLOGUE();
    const int m0 = blockIdx.x * 128;
    const int n0 = blockIdx.y * 128;
    for (int kc = 0; kc < 8; ++kc) {
        __syncthreads();
        int k0 = kc * 32;
        const float* src = (k0 < DIM) ? node : g_aggln;
        int koff = (k0 < DIM) ? k0 : (k0 - DIM);
        load_split_A(src, DIM, m0, N_NODES, koff, Ah, Al, tid);
        load_split_B(Wn1, HID, k0, n0, Bh, Bl, tid);
        __syncthreads();
        mma_chunk(Ah32, Al32, Bh32, Bl32, C, wm, wn, lane);
    }
    #pragma unroll
    for (int mf = 0; mf < 2; ++mf) {
        int row = m0 + wm * 32 + mf * 16 + gr;
        #pragma unroll
        for (int nf = 0; nf < 8; ++nf) {
            int col = n0 + wn * 64 + nf * 8 + 2 * tc;
            float b0 = bn1[col], b1 = bn1[col + 1];
            if (row < N_NODES)
                *(float2*)(g_H + row * HID + col) =
                    make_float2(swish_fast(C[mf][nf][0] + b0),
                                swish_fast(C[mf][nf][1] + b1));
            if (row + 8 < N_NODES)
                *(float2*)(g_H + (row + 8) * HID + col) =
                    make_float2(swish_fast(C[mf][nf][2] + b0),
                                swish_fast(C[mf][nf][3] + b1));
        }
    }
}

// ---------------------------------------------------------------------------
// K4b: out = LN(H @ Wn2 + bn2 + node; gnode,bnode) * mask
// ---------------------------------------------------------------------------
__global__ __launch_bounds__(256) void k4b_out(
    const float* __restrict__ node, const float* __restrict__ Wn2,
    const float* __restrict__ bn2, const float* __restrict__ gnode,
    const float* __restrict__ bnode, const float* __restrict__ mask,
    float* __restrict__ out)
{
    GEMM_PROLOGUE();
    const int m0 = blockIdx.x * 128;
    for (int kc = 0; kc < 8; ++kc) {
        __syncthreads();
        load_split_A(g_H, HID, m0, N_NODES, kc * 32, Ah, Al, tid);
        load_split_B(Wn2, DIM, kc * 32, 0, Bh, Bl, tid);
        __syncthreads();
        mma_chunk(Ah32, Al32, Bh32, Bl32, C, wm, wn, lane);
    }
    ln_epilogue(C, (float*)smraw, m0, wm, wn, w, lane,
                1.f, bn2, node, gnode, bnode, mask, out);
}

// ---------------------------------------------------------------------------
extern "C" void kernel_launch(void* const* d_in, const int* in_sizes, int n_in,
                              void* d_out, int out_size)
{
    const float* node      = (const float*)d_in[0];
    const float* edge_feat = (const float*)d_in[1];
    const float* mask      = (const float*)d_in[2];
    const float* We1       = (const float*)d_in[3];
    const float* be1       = (const float*)d_in[4];
    const float* We2       = (const float*)d_in[5];
    const float* be2       = (const float*)d_in[6];
    const float* gmsg      = (const float*)d_in[7];
    const float* bmsg      = (const float*)d_in[8];
    const float* Wn1       = (const float*)d_in[9];
    const float* bn1       = (const float*)d_in[10];
    const float* Wn2       = (const float*)d_in[11];
    const float* bn2       = (const float*)d_in[12];
    const float* gnode     = (const float*)d_in[13];
    const float* bnode     = (const float*)d_in[14];
    const int*   senders   = (const int*)d_in[15];
    float* out = (float*)d_out;

    const int mb = (N_NODES + 127) / 128;   // 391

    k1_sr     <<<dim3(mb, 4), 256>>>(node, We1, be1);
    k_ep      <<<dim3(E_EDGES / 128, 2), 256>>>(edge_feat, We1);
    k2_edge   <<<N_NODES / 8, 256>>>(senders);
    k3_aggln  <<<mb, 256>>>(We2, be2, gmsg, bmsg, mask);
    k4a_hidden<<<dim3(mb, 2), 256>>>(node, Wn1, bn1);
    k4b_out   <<<mb, 256>>>(node, Wn2, bn2, gnode, bnode, mask, out);
}

// round 3
// speedup vs baseline: 3.8527x; 1.5017x over previous
#include <cuda_runtime.h>
#include <cuda_bf16.h>
#include <math.h>

#define N_NODES 50000
#define E_EDGES 800000
#define DIM     128
#define EDIM    32
#define HID     256
#define DEG     16
#define EPS     1e-5f
#define KPAD    40                       // halves; 80B row stride (16B aligned, conflict-free)
#define TILE_HALVES (128 * KPAD)         // 5120 halves = 10240 B
#define STAGE_BYTES (4 * 128 * KPAD * 2) // Ah,Al,Bh,Bl = 40960 B
#define SMEM_BYTES  (2 * STAGE_BYTES)    // 81920 B

// ---------------- scratch (device globals; allocation-free rule) ------------
__device__ float        g_S[N_NODES * HID];
__device__ float        g_R[N_NODES * HID];
__device__ unsigned int g_EP[E_EDGES * (HID / 2)];   // bf16x2
__device__ float        g_Hagg[N_NODES * HID];
__device__ float        g_aggln[N_NODES * DIM];
__device__ float        g_H[N_NODES * HID];

__device__ __forceinline__ float swish_fast(float x) {
    float e = __expf(-x);
    return x * __fdividef(1.f, 1.f + e);
}

__device__ __forceinline__ void mma_bf16(float (&c)[4],
                                         unsigned a0, unsigned a1, unsigned a2, unsigned a3,
                                         unsigned b0, unsigned b1) {
    asm volatile(
        "mma.sync.aligned.m16n8k16.row.col.f32.bf16.bf16.f32 "
        "{%0,%1,%2,%3}, {%4,%5,%6,%7}, {%8,%9}, {%0,%1,%2,%3};"
        : "+f"(c[0]), "+f"(c[1]), "+f"(c[2]), "+f"(c[3])
        : "r"(a0), "r"(a1), "r"(a2), "r"(a3), "r"(b0), "r"(b1));
}

__device__ __forceinline__ void ldsm4(unsigned& r0, unsigned& r1, unsigned& r2, unsigned& r3,
                                      unsigned addr) {
    asm volatile("ldmatrix.sync.aligned.m8n8.x4.shared.b16 {%0,%1,%2,%3}, [%4];"
                 : "=r"(r0), "=r"(r1), "=r"(r2), "=r"(r3) : "r"(addr));
}

// ---------------- prefetch (global -> regs) ---------------------------------
struct Apf { float4 v[2]; };
struct Bpf { float v[8]; };

__device__ __forceinline__ void pf_A(Apf& p, const float* __restrict__ src, int ld,
                                     int m0, int mmax, int k0, int tid) {
    #pragma unroll
    for (int q = 0; q < 2; ++q) {
        int idx = tid + q * 512;
        int r = idx >> 3, c4 = (idx & 7) * 4;
        int grow = m0 + r;
        p.v[q] = (grow < mmax) ? *(const float4*)(src + (size_t)grow * ld + k0 + c4)
                               : make_float4(0.f, 0.f, 0.f, 0.f);
    }
}

__device__ __forceinline__ void pf_B(Bpf& p, const float* __restrict__ W, int ldw,
                                     int k0, int n0, int tid) {
    int n = tid & 127, kb = (tid >> 7) * 4;
    #pragma unroll
    for (int g = 0; g < 2; ++g)
        #pragma unroll
        for (int j = 0; j < 4; ++j)
            p.v[g * 4 + j] = W[(k0 + g * 16 + kb + j) * ldw + n0 + n];
}

// ---------------- split + STS ------------------------------------------------
__device__ __forceinline__ void sts_split4(__nv_bfloat16* Hp, __nv_bfloat16* Lp, int off,
                                           float x0, float x1, float x2, float x3) {
    __nv_bfloat162 h01 = __floats2bfloat162_rn(x0, x1);
    __nv_bfloat162 h23 = __floats2bfloat162_rn(x2, x3);
    __nv_bfloat162 l01 = __floats2bfloat162_rn(x0 - __bfloat162float(h01.x),
                                               x1 - __bfloat162float(h01.y));
    __nv_bfloat162 l23 = __floats2bfloat162_rn(x2 - __bfloat162float(h23.x),
                                               x3 - __bfloat162float(h23.y));
    *(uint2*)(Hp + off) = make_uint2(*(unsigned*)&h01, *(unsigned*)&h23);
    *(uint2*)(Lp + off) = make_uint2(*(unsigned*)&l01, *(unsigned*)&l23);
}

__device__ __forceinline__ void sts_A(const Apf& p, __nv_bfloat16* Ah, __nv_bfloat16* Al,
                                      int tid) {
    #pragma unroll
    for (int q = 0; q < 2; ++q) {
        int idx = tid + q * 512;
        int r = idx >> 3, c4 = (idx & 7) * 4;
        sts_split4(Ah, Al, r * KPAD + c4, p.v[q].x, p.v[q].y, p.v[q].z, p.v[q].w);
    }
}

__device__ __forceinline__ void sts_B(const Bpf& p, __nv_bfloat16* Bh, __nv_bfloat16* Bl,
                                      int tid) {
    int n = tid & 127, kb = (tid >> 7) * 4;
    #pragma unroll
    for (int g = 0; g < 2; ++g)
        sts_split4(Bh, Bl, n * KPAD + g * 16 + kb,
                   p.v[g * 4], p.v[g * 4 + 1], p.v[g * 4 + 2], p.v[g * 4 + 3]);
}

// ---------------- mma on one K32 chunk (warp tile 32x32) ---------------------
__device__ __forceinline__ void mma_chunk(
    const __nv_bfloat16* Ah, const __nv_bfloat16* Al,
    const __nv_bfloat16* Bh, const __nv_bfloat16* Bl,
    float (&C)[2][4][4], int wm, int wn, int lane)
{
    unsigned aH = (unsigned)__cvta_generic_to_shared(Ah);
    unsigned aL = (unsigned)__cvta_generic_to_shared(Al);
    unsigned bH = (unsigned)__cvta_generic_to_shared(Bh);
    unsigned bL = (unsigned)__cvta_generic_to_shared(Bl);

    const unsigned aoff = (unsigned)((wm * 32 + (lane & 15)) * (KPAD * 2) + (lane >> 4) * 16);
    const unsigned boff = (unsigned)((wn * 32 + ((lane >> 4) & 1) * 8 + (lane & 7)) * (KPAD * 2)
                                     + ((lane >> 3) & 1) * 16);
    #pragma unroll
    for (int ks = 0; ks < 2; ++ks) {
        const unsigned kb = ks * 32;
        unsigned ah[2][4], al[2][4];
        #pragma unroll
        for (int mf = 0; mf < 2; ++mf) {
            ldsm4(ah[mf][0], ah[mf][1], ah[mf][2], ah[mf][3],
                  aH + aoff + mf * 16 * (KPAD * 2) + kb);
            ldsm4(al[mf][0], al[mf][1], al[mf][2], al[mf][3],
                  aL + aoff + mf * 16 * (KPAD * 2) + kb);
        }
        #pragma unroll
        for (int p = 0; p < 2; ++p) {
            unsigned bh[4], bl[4];
            ldsm4(bh[0], bh[1], bh[2], bh[3], bH + boff + p * 16 * (KPAD * 2) + kb);
            ldsm4(bl[0], bl[1], bl[2], bl[3], bL + boff + p * 16 * (KPAD * 2) + kb);
            #pragma unroll
            for (int sub = 0; sub < 2; ++sub) {
                int nf = p * 2 + sub;
                unsigned b0h = bh[sub * 2], b1h = bh[sub * 2 + 1];
                unsigned b0l = bl[sub * 2], b1l = bl[sub * 2 + 1];
                #pragma unroll
                for (int mf = 0; mf < 2; ++mf) {
                    mma_bf16(C[mf][nf], ah[mf][0], ah[mf][1], ah[mf][2], ah[mf][3], b0h, b1h);
                    mma_bf16(C[mf][nf], ah[mf][0], ah[mf][1], ah[mf][2], ah[mf][3], b0l, b1l);
                    mma_bf16(C[mf][nf], al[mf][0], al[mf][1], al[mf][2], al[mf][3], b0h, b1h);
                }
            }
        }
    }
}

// ---------------- fused LayerNorm epilogue (16-warp layout) ------------------
__device__ __forceinline__ void ln_epilogue(
    float (&C)[2][4][4], float* lnbuf, int m0, int wm, int wn, int w, int lane,
    float scale, const float* __restrict__ bias, const float* __restrict__ resid,
    const float* __restrict__ gamma, const float* __restrict__ beta,
    const float* __restrict__ mask, float* __restrict__ out)
{
    const int gr = lane >> 2, tc = lane & 3;
    #pragma unroll
    for (int half = 0; half < 2; ++half) {
        __syncthreads();
        if ((wm >> 1) == half) {
            #pragma unroll
            for (int mf = 0; mf < 2; ++mf) {
                int lr = (wm & 1) * 32 + mf * 16 + gr;
                int grow = m0 + half * 64 + lr;
                #pragma unroll
                for (int nf = 0; nf < 4; ++nf) {
                    int col = wn * 32 + nf * 8 + 2 * tc;
                    float r0 = 0.f, r1 = 0.f, r2 = 0.f, r3 = 0.f;
                    if (resid) {
                        if (grow < N_NODES) {
                            r0 = resid[grow * DIM + col];
                            r1 = resid[grow * DIM + col + 1];
                        }
                        if (grow + 8 < N_NODES) {
                            r2 = resid[(grow + 8) * DIM + col];
                            r3 = resid[(grow + 8) * DIM + col + 1];
                        }
                    }
                    float b0 = bias[col], b1 = bias[col + 1];
                    lnbuf[lr * 132 + col]           = C[mf][nf][0] * scale + b0 + r0;
                    lnbuf[lr * 132 + col + 1]       = C[mf][nf][1] * scale + b1 + r1;
                    lnbuf[(lr + 8) * 132 + col]     = C[mf][nf][2] * scale + b0 + r2;
                    lnbuf[(lr + 8) * 132 + col + 1] = C[mf][nf][3] * scale + b1 + r3;
                }
            }
        }
        __syncthreads();
        {
            #pragma unroll
            for (int rw = 0; rw < 4; ++rw) {
                int m = w * 4 + rw;
                int grow = m0 + half * 64 + m;
                float x[4];
                #pragma unroll
                for (int q = 0; q < 4; ++q) x[q] = lnbuf[m * 132 + lane + 32 * q];
                float s  = x[0] + x[1] + x[2] + x[3];
                float ss = x[0]*x[0] + x[1]*x[1] + x[2]*x[2] + x[3]*x[3];
                #pragma unroll
                for (int o = 16; o > 0; o >>= 1) {
                    s  += __shfl_xor_sync(0xffffffffu, s,  o);
                    ss += __shfl_xor_sync(0xffffffffu, ss, o);
                }
                float mean = s * (1.f / DIM);
                float var  = ss * (1.f / DIM) - mean * mean;
                float inv  = rsqrtf(var + EPS);
                if (grow < N_NODES) {
                    float mk = mask[grow];
                    #pragma unroll
                    for (int q = 0; q < 4; ++q) {
                        int j = lane + 32 * q;
                        out[grow * DIM + j] = ((x[q] - mean) * inv * gamma[j] + beta[j]) * mk;
                    }
                }
            }
        }
    }
}

#define GEMM_PROLOGUE()                                                        \
    extern __shared__ __align__(16) unsigned char smraw[];                     \
    __nv_bfloat16* stA_h[2]; __nv_bfloat16* stA_l[2];                          \
    __nv_bfloat16* stB_h[2]; __nv_bfloat16* stB_l[2];                          \
    _Pragma("unroll") for (int s = 0; s < 2; ++s) {                            \
        __nv_bfloat16* b = (__nv_bfloat16*)(smraw + s * STAGE_BYTES);          \
        stA_h[s] = b; stA_l[s] = b + TILE_HALVES;                              \
        stB_h[s] = b + 2 * TILE_HALVES; stB_l[s] = b + 3 * TILE_HALVES;        \
    }                                                                          \
    const int tid = threadIdx.x;                                               \
    const int w = tid >> 5, lane = tid & 31;                                   \
    const int wm = w & 3, wn = w >> 2;                                         \
    const int gr = lane >> 2, tc = lane & 3;                                   \
    (void)gr; (void)tc;                                                        \
    float C[2][4][4];                                                          \
    _Pragma("unroll") for (int mf = 0; mf < 2; ++mf)                           \
        _Pragma("unroll") for (int nf = 0; nf < 4; ++nf)                       \
            _Pragma("unroll") for (int i = 0; i < 4; ++i) C[mf][nf][i] = 0.f;

// pipeline over KT chunks; ASRC(kc) must give {src ptr, ld, koff}
#define GEMM_PIPELINE(KT, PF_A_CALL, PF_B_CALL)                                \
    {                                                                          \
        Apf pa; Bpf pb;                                                        \
        int kc = 0;                                                            \
        PF_A_CALL; PF_B_CALL;                                                  \
        sts_A(pa, stA_h[0], stA_l[0], tid);                                    \
        sts_B(pb, stB_h[0], stB_l[0], tid);                                    \
        for (kc = 0; kc < (KT); ++kc) {                                        \
            int nxt = kc + 1;                                                  \
            if (nxt < (KT)) { int kc_s = kc; kc = nxt;                         \
                PF_A_CALL; PF_B_CALL; kc = kc_s; }                             \
            __syncthreads();                                                   \
            int cur = kc & 1;                                                  \
            mma_chunk(stA_h[cur], stA_l[cur], stB_h[cur], stB_l[cur],          \
                      C, wm, wn, lane);                                        \
            if (nxt < (KT)) {                                                  \
                sts_A(pa, stA_h[nxt & 1], stA_l[nxt & 1], tid);                \
                sts_B(pb, stB_h[nxt & 1], stB_l[nxt & 1], tid);                \
            }                                                                  \
        }                                                                      \
    }

// ---------------------------------------------------------------------------
// K1: S = node@We1[0:128,:] ; R = node@We1[128:256,:] + be1.  grid (391,4)
// ---------------------------------------------------------------------------
__global__ __launch_bounds__(512, 1) void k1_sr(
    const float* __restrict__ node, const float* __restrict__ We1,
    const float* __restrict__ be1)
{
    GEMM_PROLOGUE();
    const int m0 = blockIdx.x * 128;
    const int which = blockIdx.y >> 1;
    const int n0 = (blockIdx.y & 1) * 128;
    const float* W = We1 + which * DIM * HID;

    GEMM_PIPELINE(4,
        pf_A(pa, node, DIM, m0, N_NODES, kc * 32, tid),
        pf_B(pb, W, HID, kc * 32, n0, tid));

    float* outp = which ? g_R : g_S;
    #pragma unroll
    for (int mf = 0; mf < 2; ++mf) {
        int row = m0 + wm * 32 + mf * 16 + gr;
        #pragma unroll
        for (int nf = 0; nf < 4; ++nf) {
            int col = n0 + wn * 32 + nf * 8 + 2 * tc;
            float b0 = which ? be1[col] : 0.f;
            float b1 = which ? be1[col + 1] : 0.f;
            if (row < N_NODES)
                *(float2*)(outp + row * HID + col) =
                    make_float2(C[mf][nf][0] + b0, C[mf][nf][1] + b1);
            if (row + 8 < N_NODES)
                *(float2*)(outp + (row + 8) * HID + col) =
                    make_float2(C[mf][nf][2] + b0, C[mf][nf][3] + b1);
        }
    }
}

// ---------------------------------------------------------------------------
// K_EP: EP = edge_feat @ We1[256:288,:] -> bf16x2. grid (6250,2), K=32
// ---------------------------------------------------------------------------
__global__ __launch_bounds__(512, 1) void k_ep(
    const float* __restrict__ edge_feat, const float* __restrict__ We1)
{
    GEMM_PROLOGUE();
    const int m0 = blockIdx.x * 128;
    const int n0 = blockIdx.y * 128;
    const float* W = We1 + 2 * DIM * HID;

    GEMM_PIPELINE(1,
        pf_A(pa, edge_feat, EDIM, m0, E_EDGES, kc * 32, tid),
        pf_B(pb, W, HID, kc * 32, n0, tid));

    #pragma unroll
    for (int mf = 0; mf < 2; ++mf) {
        int row = m0 + wm * 32 + mf * 16 + gr;
        #pragma unroll
        for (int nf = 0; nf < 4; ++nf) {
            int col = n0 + wn * 32 + nf * 8 + 2 * tc;
            __nv_bfloat162 t0 = __floats2bfloat162_rn(C[mf][nf][0], C[mf][nf][1]);
            __nv_bfloat162 t1 = __floats2bfloat162_rn(C[mf][nf][2], C[mf][nf][3]);
            g_EP[row * 128 + (col >> 1)]       = *(unsigned*)&t0;
            g_EP[(row + 8) * 128 + (col >> 1)] = *(unsigned*)&t1;
        }
    }
}

// ---------------------------------------------------------------------------
// K2: Hagg[n] = sum over 16 edges of swish(S[snd] + R[n] + EP[e])
// ---------------------------------------------------------------------------
__global__ __launch_bounds__(256) void k2_edge(const int* __restrict__ senders)
{
    const int tid = threadIdx.x, w = tid >> 5, lane = tid & 31;
    const int n = blockIdx.x * 8 + w;
    const int e0 = n * DEG;
    const int cb = lane * 8;

    float rr[8];
    {
        const float4* r4 = (const float4*)(g_R + n * HID + cb);
        *(float4*)&rr[0] = r4[0]; *(float4*)&rr[4] = r4[1];
    }
    float hacc[8];
    #pragma unroll
    for (int i = 0; i < 8; ++i) hacc[i] = 0.f;

    int sidx[16];
    #pragma unroll
    for (int e = 0; e < 16; ++e) sidx[e] = senders[e0 + e];

    #pragma unroll
    for (int e = 0; e < 16; ++e) {
        const float4* s4 = (const float4*)(g_S + sidx[e] * HID + cb);
        float4 s0 = s4[0], s1 = s4[1];
        uint4 ep = *(const uint4*)(g_EP + (e0 + e) * 128 + lane * 4);
        float sv[8] = {s0.x, s0.y, s0.z, s0.w, s1.x, s1.y, s1.z, s1.w};
        unsigned epu[4] = {ep.x, ep.y, ep.z, ep.w};
        #pragma unroll
        for (int j = 0; j < 4; ++j) {
            __nv_bfloat162 b = *(__nv_bfloat162*)&epu[j];
            float p0 = sv[2 * j]     + rr[2 * j]     + __bfloat162float(b.x);
            float p1 = sv[2 * j + 1] + rr[2 * j + 1] + __bfloat162float(b.y);
            hacc[2 * j]     += swish_fast(p0);
            hacc[2 * j + 1] += swish_fast(p1);
        }
    }
    float4* o4 = (float4*)(g_Hagg + n * HID + cb);
    o4[0] = *(float4*)&hacc[0]; o4[1] = *(float4*)&hacc[4];
}

// ---------------------------------------------------------------------------
// K3: aggln = LN(Hagg @ We2 / 16 + be2) * mask
// ---------------------------------------------------------------------------
__global__ __launch_bounds__(512, 1) void k3_aggln(
    const float* __restrict__ We2, const float* __restrict__ be2,
    const float* __restrict__ gmsg, const float* __restrict__ bmsg,
    const float* __restrict__ mask)
{
    GEMM_PROLOGUE();
    const int m0 = blockIdx.x * 128;
    GEMM_PIPELINE(8,
        pf_A(pa, g_Hagg, HID, m0, N_NODES, kc * 32, tid),
        pf_B(pb, We2, DIM, kc * 32, 0, tid));
    ln_epilogue(C, (float*)smraw, m0, wm, wn, w, lane,
                1.f / DEG, be2, nullptr, gmsg, bmsg, mask, g_aggln);
}

// ---------------------------------------------------------------------------
// K4a: H = swish([node | aggln] @ Wn1 + bn1). grid (391,2)
// ---------------------------------------------------------------------------
__global__ __launch_bounds__(512, 1) void k4a_hidden(
    const float* __restrict__ node, const float* __restrict__ Wn1,
    const float* __restrict__ bn1)
{
    GEMM_PROLOGUE();
    const int m0 = blockIdx.x * 128;
    const int n0 = blockIdx.y * 128;
    GEMM_PIPELINE(8,
        pf_A(pa, (kc < 4) ? node : (const float*)g_aggln, DIM, m0, N_NODES,
             (kc < 4) ? kc * 32 : (kc - 4) * 32, tid),
        pf_B(pb, Wn1, HID, kc * 32, n0, tid));

    #pragma unroll
    for (int mf = 0; mf < 2; ++mf) {
        int row = m0 + wm * 32 + mf * 16 + gr;
        #pragma unroll
        for (int nf = 0; nf < 4; ++nf) {
            int col = n0 + wn * 32 + nf * 8 + 2 * tc;
            float b0 = bn1[col], b1 = bn1[col + 1];
            if (row < N_NODES)
                *(float2*)(g_H + row * HID + col) =
                    make_float2(swish_fast(C[mf][nf][0] + b0),
                                swish_fast(C[mf][nf][1] + b1));
            if (row + 8 < N_NODES)
                *(float2*)(g_H + (row + 8) * HID + col) =
                    make_float2(swish_fast(C[mf][nf][2] + b0),
                                swish_fast(C[mf][nf][3] + b1));
        }
    }
}

// ---------------------------------------------------------------------------
// K4b: out = LN(H @ Wn2 + bn2 + node) * mask
// ---------------------------------------------------------------------------
__global__ __launch_bounds__(512, 1) void k4b_out(
    const float* __restrict__ node, const float* __restrict__ Wn2,
    const float* __restrict__ bn2, const float* __restrict__ gnode,
    const float* __restrict__ bnode, const float* __restrict__ mask,
    float* __restrict__ out)
{
    GEMM_PROLOGUE();
    const int m0 = blockIdx.x * 128;
    GEMM_PIPELINE(8,
        pf_A(pa, g_H, HID, m0, N_NODES, kc * 32, tid),
        pf_B(pb, Wn2, DIM, kc * 32, 0, tid));
    ln_epilogue(C, (float*)smraw, m0, wm, wn, w, lane,
                1.f, bn2, node, gnode, bnode, mask, out);
}

// ---------------------------------------------------------------------------
extern "C" void kernel_launch(void* const* d_in, const int* in_sizes, int n_in,
                              void* d_out, int out_size)
{
    const float* node      = (const float*)d_in[0];
    const float* edge_feat = (const float*)d_in[1];
    const float* mask      = (const float*)d_in[2];
    const float* We1       = (const float*)d_in[3];
    const float* be1       = (const float*)d_in[4];
    const float* We2       = (const float*)d_in[5];
    const float* be2       = (const float*)d_in[6];
    const float* gmsg      = (const float*)d_in[7];
    const float* bmsg      = (const float*)d_in[8];
    const float* Wn1       = (const float*)d_in[9];
    const float* bn1       = (const float*)d_in[10];
    const float* Wn2       = (const float*)d_in[11];
    const float* bn2       = (const float*)d_in[12];
    const float* gnode     = (const float*)d_in[13];
    const float* bnode     = (const float*)d_in[14];
    const int*   senders   = (const int*)d_in[15];
    float* out = (float*)d_out;

    cudaFuncSetAttribute(k1_sr,      cudaFuncAttributeMaxDynamicSharedMemorySize, SMEM_BYTES);
    cudaFuncSetAttribute(k_ep,       cudaFuncAttributeMaxDynamicSharedMemorySize, SMEM_BYTES);
    cudaFuncSetAttribute(k3_aggln,   cudaFuncAttributeMaxDynamicSharedMemorySize, SMEM_BYTES);
    cudaFuncSetAttribute(k4a_hidden, cudaFuncAttributeMaxDynamicSharedMemorySize, SMEM_BYTES);
    cudaFuncSetAttribute(k4b_out,    cudaFuncAttributeMaxDynamicSharedMemorySize, SMEM_BYTES);

    const int mb = (N_NODES + 127) / 128;   // 391

    k1_sr     <<<dim3(mb, 4), 512, SMEM_BYTES>>>(node, We1, be1);
    k_ep      <<<dim3(E_EDGES / 128, 2), 512, SMEM_BYTES>>>(edge_feat, We1);
    k2_edge   <<<N_NODES / 8, 256>>>(senders);
    k3_aggln  <<<mb, 512, SMEM_BYTES>>>(We2, be2, gmsg, bmsg, mask);
    k4a_hidden<<<dim3(mb, 2), 512, SMEM_BYTES>>>(node, Wn1, bn1);
    k4b_out   <<<mb, 512, SMEM_BYTES>>>(node, Wn2, bn2, gnode, bnode, mask, out);
}

// round 4
// speedup vs baseline: 3.9781x; 1.0325x over previous
#include <cuda_runtime.h>
#include <cuda_bf16.h>
#include <math.h>

#define N_NODES 50000
#define E_EDGES 800000
#define DIM     128
#define EDIM    32
#define HID     256
#define DEG     16
#define EPS     1e-5f
#define KPAD    40                       // halves; 80B row stride (16B aligned, conflict-free)
#define TILE_HALVES (128 * KPAD)         // 5120 halves = 10240 B
#define STAGE_BYTES (4 * 128 * KPAD * 2) // Ah,Al,Bh,Bl = 40960 B
#define SMEM_BYTES  (2 * STAGE_BYTES)    // 81920 B

// ---------------- scratch (device globals; allocation-free rule) ------------
__device__ float g_S[N_NODES * HID];
__device__ float g_R[N_NODES * HID];
__device__ float g_Hagg[N_NODES * HID];
__device__ float g_aggln[N_NODES * DIM];
__device__ float g_H[N_NODES * HID];

__device__ __forceinline__ float swish_fast(float x) {
    float e = __expf(-x);
    return x * __fdividef(1.f, 1.f + e);
}

__device__ __forceinline__ void mma_bf16(float (&c)[4],
                                         unsigned a0, unsigned a1, unsigned a2, unsigned a3,
                                         unsigned b0, unsigned b1) {
    asm volatile(
        "mma.sync.aligned.m16n8k16.row.col.f32.bf16.bf16.f32 "
        "{%0,%1,%2,%3}, {%4,%5,%6,%7}, {%8,%9}, {%0,%1,%2,%3};"
        : "+f"(c[0]), "+f"(c[1]), "+f"(c[2]), "+f"(c[3])
        : "r"(a0), "r"(a1), "r"(a2), "r"(a3), "r"(b0), "r"(b1));
}

__device__ __forceinline__ void ldsm4(unsigned& r0, unsigned& r1, unsigned& r2, unsigned& r3,
                                      unsigned addr) {
    asm volatile("ldmatrix.sync.aligned.m8n8.x4.shared.b16 {%0,%1,%2,%3}, [%4];"
                 : "=r"(r0), "=r"(r1), "=r"(r2), "=r"(r3) : "r"(addr));
}

// ---------------- prefetch (global -> regs) ---------------------------------
struct Apf { float4 v[2]; };
struct Bpf { float v[8]; };

__device__ __forceinline__ void pf_A(Apf& p, const float* __restrict__ src, int ld,
                                     int m0, int mmax, int k0, int tid) {
    #pragma unroll
    for (int q = 0; q < 2; ++q) {
        int idx = tid + q * 512;
        int r = idx >> 3, c4 = (idx & 7) * 4;
        int grow = m0 + r;
        p.v[q] = (grow < mmax) ? *(const float4*)(src + (size_t)grow * ld + k0 + c4)
                               : make_float4(0.f, 0.f, 0.f, 0.f);
    }
}

__device__ __forceinline__ void pf_B(Bpf& p, const float* __restrict__ W, int ldw,
                                     int k0, int n0, int tid) {
    int n = tid & 127, kb = (tid >> 7) * 4;
    #pragma unroll
    for (int g = 0; g < 2; ++g)
        #pragma unroll
        for (int j = 0; j < 4; ++j)
            p.v[g * 4 + j] = W[(k0 + g * 16 + kb + j) * ldw + n0 + n];
}

// ---------------- split + STS ------------------------------------------------
__device__ __forceinline__ void sts_split4(__nv_bfloat16* Hp, __nv_bfloat16* Lp, int off,
                                           float x0, float x1, float x2, float x3) {
    __nv_bfloat162 h01 = __floats2bfloat162_rn(x0, x1);
    __nv_bfloat162 h23 = __floats2bfloat162_rn(x2, x3);
    __nv_bfloat162 l01 = __floats2bfloat162_rn(x0 - __bfloat162float(h01.x),
                                               x1 - __bfloat162float(h01.y));
    __nv_bfloat162 l23 = __floats2bfloat162_rn(x2 - __bfloat162float(h23.x),
                                               x3 - __bfloat162float(h23.y));
    *(uint2*)(Hp + off) = make_uint2(*(unsigned*)&h01, *(unsigned*)&h23);
    *(uint2*)(Lp + off) = make_uint2(*(unsigned*)&l01, *(unsigned*)&l23);
}

__device__ __forceinline__ void sts_A(const Apf& p, __nv_bfloat16* Ah, __nv_bfloat16* Al,
                                      int tid) {
    #pragma unroll
    for (int q = 0; q < 2; ++q) {
        int idx = tid + q * 512;
        int r = idx >> 3, c4 = (idx & 7) * 4;
        sts_split4(Ah, Al, r * KPAD + c4, p.v[q].x, p.v[q].y, p.v[q].z, p.v[q].w);
    }
}

__device__ __forceinline__ void sts_B(const Bpf& p, __nv_bfloat16* Bh, __nv_bfloat16* Bl,
                                      int tid) {
    int n = tid & 127, kb = (tid >> 7) * 4;
    #pragma unroll
    for (int g = 0; g < 2; ++g)
        sts_split4(Bh, Bl, n * KPAD + g * 16 + kb,
                   p.v[g * 4], p.v[g * 4 + 1], p.v[g * 4 + 2], p.v[g * 4 + 3]);
}

// ---------------- mma on one K32 chunk (warp tile 32x32) ---------------------
__device__ __forceinline__ void mma_chunk(
    const __nv_bfloat16* Ah, const __nv_bfloat16* Al,
    const __nv_bfloat16* Bh, const __nv_bfloat16* Bl,
    float (&C)[2][4][4], int wm, int wn, int lane)
{
    unsigned aH = (unsigned)__cvta_generic_to_shared(Ah);
    unsigned aL = (unsigned)__cvta_generic_to_shared(Al);
    unsigned bH = (unsigned)__cvta_generic_to_shared(Bh);
    unsigned bL = (unsigned)__cvta_generic_to_shared(Bl);

    const unsigned aoff = (unsigned)((wm * 32 + (lane & 15)) * (KPAD * 2) + (lane >> 4) * 16);
    const unsigned boff = (unsigned)((wn * 32 + ((lane >> 4) & 1) * 8 + (lane & 7)) * (KPAD * 2)
                                     + ((lane >> 3) & 1) * 16);
    #pragma unroll
    for (int ks = 0; ks < 2; ++ks) {
        const unsigned kb = ks * 32;
        unsigned ah[2][4], al[2][4];
        #pragma unroll
        for (int mf = 0; mf < 2; ++mf) {
            ldsm4(ah[mf][0], ah[mf][1], ah[mf][2], ah[mf][3],
                  aH + aoff + mf * 16 * (KPAD * 2) + kb);
            ldsm4(al[mf][0], al[mf][1], al[mf][2], al[mf][3],
                  aL + aoff + mf * 16 * (KPAD * 2) + kb);
        }
        #pragma unroll
        for (int p = 0; p < 2; ++p) {
            unsigned bh[4], bl[4];
            ldsm4(bh[0], bh[1], bh[2], bh[3], bH + boff + p * 16 * (KPAD * 2) + kb);
            ldsm4(bl[0], bl[1], bl[2], bl[3], bL + boff + p * 16 * (KPAD * 2) + kb);
            #pragma unroll
            for (int sub = 0; sub < 2; ++sub) {
                int nf = p * 2 + sub;
                unsigned b0h = bh[sub * 2], b1h = bh[sub * 2 + 1];
                unsigned b0l = bl[sub * 2], b1l = bl[sub * 2 + 1];
                #pragma unroll
                for (int mf = 0; mf < 2; ++mf) {
                    mma_bf16(C[mf][nf], ah[mf][0], ah[mf][1], ah[mf][2], ah[mf][3], b0h, b1h);
                    mma_bf16(C[mf][nf], ah[mf][0], ah[mf][1], ah[mf][2], ah[mf][3], b0l, b1l);
                    mma_bf16(C[mf][nf], al[mf][0], al[mf][1], al[mf][2], al[mf][3], b0h, b1h);
                }
            }
        }
    }
}

// ---------------- fused LayerNorm epilogue (16-warp layout) ------------------
__device__ __forceinline__ void ln_epilogue(
    float (&C)[2][4][4], float* lnbuf, int m0, int wm, int wn, int w, int lane,
    float scale, const float* __restrict__ bias, const float* __restrict__ resid,
    const float* __restrict__ gamma, const float* __restrict__ beta,
    const float* __restrict__ mask, float* __restrict__ out)
{
    const int gr = lane >> 2, tc = lane & 3;
    #pragma unroll
    for (int half = 0; half < 2; ++half) {
        __syncthreads();
        if ((wm >> 1) == half) {
            #pragma unroll
            for (int mf = 0; mf < 2; ++mf) {
                int lr = (wm & 1) * 32 + mf * 16 + gr;
                int grow = m0 + half * 64 + lr;
                #pragma unroll
                for (int nf = 0; nf < 4; ++nf) {
                    int col = wn * 32 + nf * 8 + 2 * tc;
                    float r0 = 0.f, r1 = 0.f, r2 = 0.f, r3 = 0.f;
                    if (resid) {
                        if (grow < N_NODES) {
                            r0 = resid[grow * DIM + col];
                            r1 = resid[grow * DIM + col + 1];
                        }
                        if (grow + 8 < N_NODES) {
                            r2 = resid[(grow + 8) * DIM + col];
                            r3 = resid[(grow + 8) * DIM + col + 1];
                        }
                    }
                    float b0 = bias[col], b1 = bias[col + 1];
                    lnbuf[lr * 132 + col]           = C[mf][nf][0] * scale + b0 + r0;
                    lnbuf[lr * 132 + col + 1]       = C[mf][nf][1] * scale + b1 + r1;
                    lnbuf[(lr + 8) * 132 + col]     = C[mf][nf][2] * scale + b0 + r2;
                    lnbuf[(lr + 8) * 132 + col + 1] = C[mf][nf][3] * scale + b1 + r3;
                }
            }
        }
        __syncthreads();
        {
            #pragma unroll
            for (int rw = 0; rw < 4; ++rw) {
                int m = w * 4 + rw;
                int grow = m0 + half * 64 + m;
                float x[4];
                #pragma unroll
                for (int q = 0; q < 4; ++q) x[q] = lnbuf[m * 132 + lane + 32 * q];
                float s  = x[0] + x[1] + x[2] + x[3];
                float ss = x[0]*x[0] + x[1]*x[1] + x[2]*x[2] + x[3]*x[3];
                #pragma unroll
                for (int o = 16; o > 0; o >>= 1) {
                    s  += __shfl_xor_sync(0xffffffffu, s,  o);
                    ss += __shfl_xor_sync(0xffffffffu, ss, o);
                }
                float mean = s * (1.f / DIM);
                float var  = ss * (1.f / DIM) - mean * mean;
                float inv  = rsqrtf(var + EPS);
                if (grow < N_NODES) {
                    float mk = mask[grow];
                    #pragma unroll
                    for (int q = 0; q < 4; ++q) {
                        int j = lane + 32 * q;
                        out[grow * DIM + j] = ((x[q] - mean) * inv * gamma[j] + beta[j]) * mk;
                    }
                }
            }
        }
    }
}

#define GEMM_PROLOGUE()                                                        \
    extern __shared__ __align__(16) unsigned char smraw[];                     \
    __nv_bfloat16* stA_h[2]; __nv_bfloat16* stA_l[2];                          \
    __nv_bfloat16* stB_h[2]; __nv_bfloat16* stB_l[2];                          \
    _Pragma("unroll") for (int s = 0; s < 2; ++s) {                            \
        __nv_bfloat16* b = (__nv_bfloat16*)(smraw + s * STAGE_BYTES);          \
        stA_h[s] = b; stA_l[s] = b + TILE_HALVES;                              \
        stB_h[s] = b + 2 * TILE_HALVES; stB_l[s] = b + 3 * TILE_HALVES;        \
    }                                                                          \
    const int tid = threadIdx.x;                                               \
    const int w = tid >> 5, lane = tid & 31;                                   \
    const int wm = w & 3, wn = w >> 2;                                         \
    const int gr = lane >> 2, tc = lane & 3;                                   \
    (void)gr; (void)tc;                                                        \
    float C[2][4][4];                                                          \
    _Pragma("unroll") for (int mf = 0; mf < 2; ++mf)                           \
        _Pragma("unroll") for (int nf = 0; nf < 4; ++nf)                       \
            _Pragma("unroll") for (int i = 0; i < 4; ++i) C[mf][nf][i] = 0.f;

#define GEMM_PIPELINE(KT, PF_A_CALL, PF_B_CALL)                                \
    {                                                                          \
        Apf pa; Bpf pb;                                                        \
        int kc = 0;                                                            \
        PF_A_CALL; PF_B_CALL;                                                  \
        sts_A(pa, stA_h[0], stA_l[0], tid);                                    \
        sts_B(pb, stB_h[0], stB_l[0], tid);                                    \
        for (kc = 0; kc < (KT); ++kc) {                                        \
            int nxt = kc + 1;                                                  \
            if (nxt < (KT)) { int kc_s = kc; kc = nxt;                         \
                PF_A_CALL; PF_B_CALL; kc = kc_s; }                             \
            __syncthreads();                                                   \
            int cur = kc & 1;                                                  \
            mma_chunk(stA_h[cur], stA_l[cur], stB_h[cur], stB_l[cur],          \
                      C, wm, wn, lane);                                        \
            if (nxt < (KT)) {                                                  \
                sts_A(pa, stA_h[nxt & 1], stA_l[nxt & 1], tid);                \
                sts_B(pb, stB_h[nxt & 1], stB_l[nxt & 1], tid);                \
            }                                                                  \
        }                                                                      \
    }

// ---------------------------------------------------------------------------
// K1: S = node@We1[0:128,:] ; R = node@We1[128:256,:] + be1.  grid (391,4)
// ---------------------------------------------------------------------------
__global__ __launch_bounds__(512, 1) void k1_sr(
    const float* __restrict__ node, const float* __restrict__ We1,
    const float* __restrict__ be1)
{
    GEMM_PROLOGUE();
    const int m0 = blockIdx.x * 128;
    const int which = blockIdx.y >> 1;
    const int n0 = (blockIdx.y & 1) * 128;
    const float* W = We1 + which * DIM * HID;

    GEMM_PIPELINE(4,
        pf_A(pa, node, DIM, m0, N_NODES, kc * 32, tid),
        pf_B(pb, W, HID, kc * 32, n0, tid));

    float* outp = which ? g_R : g_S;
    #pragma unroll
    for (int mf = 0; mf < 2; ++mf) {
        int row = m0 + wm * 32 + mf * 16 + gr;
        #pragma unroll
        for (int nf = 0; nf < 4; ++nf) {
            int col = n0 + wn * 32 + nf * 8 + 2 * tc;
            float b0 = which ? be1[col] : 0.f;
            float b1 = which ? be1[col + 1] : 0.f;
            if (row < N_NODES)
                *(float2*)(outp + row * HID + col) =
                    make_float2(C[mf][nf][0] + b0, C[mf][nf][1] + b1);
            if (row + 8 < N_NODES)
                *(float2*)(outp + (row + 8) * HID + col) =
                    make_float2(C[mf][nf][2] + b0, C[mf][nf][3] + b1);
        }
    }
}

// ---------------------------------------------------------------------------
// K2F: fused edge projection + gather + swish + per-node reduce.
// grid (E/128 = 6250, 2). CTA: 128 edges (= 8 nodes) x 128 cols. K = 32.
// Hagg[n][col] = sum_{16 edges of n} swish(EP[e][col] + S[snd[e]][col] + R[n][col])
// ---------------------------------------------------------------------------
__global__ __launch_bounds__(512, 1) void k2f(
    const float* __restrict__ edge_feat, const int* __restrict__ senders,
    const float* __restrict__ We1)
{
    __shared__ __align__(16) unsigned char smstage[STAGE_BYTES];  // 40 KB
    __shared__ int   ss[128];
    __shared__ float Rs[8][128];

    __nv_bfloat16* Ah = (__nv_bfloat16*)smstage;
    __nv_bfloat16* Al = Ah + TILE_HALVES;
    __nv_bfloat16* Bh = Al + TILE_HALVES;
    __nv_bfloat16* Bl = Bh + TILE_HALVES;

    const int tid = threadIdx.x;
    const int w = tid >> 5, lane = tid & 31;
    const int wm = w & 3, wn = w >> 2;
    const int gr = lane >> 2, tc = lane & 3;

    const int e0 = blockIdx.x * 128;
    const int n0 = blockIdx.y * 128;
    const int node0 = e0 >> 4;                       // 8 nodes per CTA
    const float* W = We1 + 2 * DIM * HID;            // edge-feature rows of We1

    // stage tiles + metadata
    {
        Apf pa; pf_A(pa, edge_feat, EDIM, e0, E_EDGES, 0, tid);
        Bpf pb; pf_B(pb, W, HID, 0, n0, tid);
        sts_A(pa, Ah, Al, tid);
        sts_B(pb, Bh, Bl, tid);
    }
    if (tid < 128) ss[tid] = senders[e0 + tid];
    #pragma unroll
    for (int q = 0; q < 2; ++q) {
        int idx = tid + q * 512;
        int r = idx >> 7, c = idx & 127;
        Rs[r][c] = g_R[(size_t)(node0 + r) * HID + n0 + c];
    }
    __syncthreads();

    float C[2][4][4];
    #pragma unroll
    for (int mf = 0; mf < 2; ++mf)
        #pragma unroll
        for (int nf = 0; nf < 4; ++nf)
            #pragma unroll
            for (int i = 0; i < 4; ++i) C[mf][nf][i] = 0.f;

    mma_chunk(Ah, Al, Bh, Bl, C, wm, wn, lane);

    // epilogue: gather S, add R, swish, reduce 16 rows -> node
    #pragma unroll
    for (int mf = 0; mf < 2; ++mf) {
        const int lrow = wm * 32 + mf * 16;          // node-local row base
        const int nloc = lrow >> 4;                  // local node 0..7
        const int snd0 = ss[lrow + gr];
        const int snd1 = ss[lrow + gr + 8];
        const float* s0p = g_S + (size_t)snd0 * HID + n0;
        const float* s1p = g_S + (size_t)snd1 * HID + n0;
        #pragma unroll
        for (int nf = 0; nf < 4; ++nf) {
            const int colL = wn * 32 + nf * 8 + 2 * tc;
            float2 s0 = *(const float2*)(s0p + colL);
            float2 s1 = *(const float2*)(s1p + colL);
            float r0 = Rs[nloc][colL], r1 = Rs[nloc][colL + 1];
            float h0 = swish_fast(C[mf][nf][0] + s0.x + r0)
                     + swish_fast(C[mf][nf][2] + s1.x + r0);
            float h1 = swish_fast(C[mf][nf][1] + s0.y + r1)
                     + swish_fast(C[mf][nf][3] + s1.y + r1);
            #pragma unroll
            for (int o = 4; o <= 16; o <<= 1) {
                h0 += __shfl_xor_sync(0xffffffffu, h0, o);
                h1 += __shfl_xor_sync(0xffffffffu, h1, o);
            }
            if (gr == 0)
                *(float2*)(g_Hagg + (size_t)(node0 + nloc) * HID + n0 + colL) =
                    make_float2(h0, h1);
        }
    }
}

// ---------------------------------------------------------------------------
// K3: aggln = LN(Hagg @ We2 / 16 + be2) * mask
// ---------------------------------------------------------------------------
__global__ __launch_bounds__(512, 1) void k3_aggln(
    const float* __restrict__ We2, const float* __restrict__ be2,
    const float* __restrict__ gmsg, const float* __restrict__ bmsg,
    const float* __restrict__ mask)
{
    GEMM_PROLOGUE();
    const int m0 = blockIdx.x * 128;
    GEMM_PIPELINE(8,
        pf_A(pa, g_Hagg, HID, m0, N_NODES, kc * 32, tid),
        pf_B(pb, We2, DIM, kc * 32, 0, tid));
    ln_epilogue(C, (float*)smraw, m0, wm, wn, w, lane,
                1.f / DEG, be2, nullptr, gmsg, bmsg, mask, g_aggln);
}

// ---------------------------------------------------------------------------
// K4a: H = swish([node | aggln] @ Wn1 + bn1). grid (391,2)
// ---------------------------------------------------------------------------
__global__ __launch_bounds__(512, 1) void k4a_hidden(
    const float* __restrict__ node, const float* __restrict__ Wn1,
    const float* __restrict__ bn1)
{
    GEMM_PROLOGUE();
    const int m0 = blockIdx.x * 128;
    const int n0 = blockIdx.y * 128;
    GEMM_PIPELINE(8,
        pf_A(pa, (kc < 4) ? node : (const float*)g_aggln, DIM, m0, N_NODES,
             (kc < 4) ? kc * 32 : (kc - 4) * 32, tid),
        pf_B(pb, Wn1, HID, kc * 32, n0, tid));

    #pragma unroll
    for (int mf = 0; mf < 2; ++mf) {
        int row = m0 + wm * 32 + mf * 16 + gr;
        #pragma unroll
        for (int nf = 0; nf < 4; ++nf) {
            int col = n0 + wn * 32 + nf * 8 + 2 * tc;
            float b0 = bn1[col], b1 = bn1[col + 1];
            if (row < N_NODES)
                *(float2*)(g_H + row * HID + col) =
                    make_float2(swish_fast(C[mf][nf][0] + b0),
                                swish_fast(C[mf][nf][1] + b1));
            if (row + 8 < N_NODES)
                *(float2*)(g_H + (row + 8) * HID + col) =
                    make_float2(swish_fast(C[mf][nf][2] + b0),
                                swish_fast(C[mf][nf][3] + b1));
        }
    }
}

// ---------------------------------------------------------------------------
// K4b: out = LN(H @ Wn2 + bn2 + node) * mask
// ---------------------------------------------------------------------------
__global__ __launch_bounds__(512, 1) void k4b_out(
    const float* __restrict__ node, const float* __restrict__ Wn2,
    const float* __restrict__ bn2, const float* __restrict__ gnode,
    const float* __restrict__ bnode, const float* __restrict__ mask,
    float* __restrict__ out)
{
    GEMM_PROLOGUE();
    const int m0 = blockIdx.x * 128;
    GEMM_PIPELINE(8,
        pf_A(pa, g_H, HID, m0, N_NODES, kc * 32, tid),
        pf_B(pb, Wn2, DIM, kc * 32, 0, tid));
    ln_epilogue(C, (float*)smraw, m0, wm, wn, w, lane,
                1.f, bn2, node, gnode, bnode, mask, out);
}

// ---------------------------------------------------------------------------
extern "C" void kernel_launch(void* const* d_in, const int* in_sizes, int n_in,
                              void* d_out, int out_size)
{
    const float* node      = (const float*)d_in[0];
    const float* edge_feat = (const float*)d_in[1];
    const float* mask      = (const float*)d_in[2];
    const float* We1       = (const float*)d_in[3];
    const float* be1       = (const float*)d_in[4];
    const float* We2       = (const float*)d_in[5];
    const float* be2       = (const float*)d_in[6];
    const float* gmsg      = (const float*)d_in[7];
    const float* bmsg      = (const float*)d_in[8];
    const float* Wn1       = (const float*)d_in[9];
    const float* bn1       = (const float*)d_in[10];
    const float* Wn2       = (const float*)d_in[11];
    const float* bn2       = (const float*)d_in[12];
    const float* gnode     = (const float*)d_in[13];
    const float* bnode     = (const float*)d_in[14];
    const int*   senders   = (const int*)d_in[15];
    float* out = (float*)d_out;

    cudaFuncSetAttribute(k1_sr,      cudaFuncAttributeMaxDynamicSharedMemorySize, SMEM_BYTES);
    cudaFuncSetAttribute(k3_aggln,   cudaFuncAttributeMaxDynamicSharedMemorySize, SMEM_BYTES);
    cudaFuncSetAttribute(k4a_hidden, cudaFuncAttributeMaxDynamicSharedMemorySize, SMEM_BYTES);
    cudaFuncSetAttribute(k4b_out,    cudaFuncAttributeMaxDynamicSharedMemorySize, SMEM_BYTES);

    const int mb = (N_NODES + 127) / 128;   // 391

    k1_sr     <<<dim3(mb, 4), 512, SMEM_BYTES>>>(node, We1, be1);
    k2f       <<<dim3(E_EDGES / 128, 2), 512>>>(edge_feat, senders, We1);
    k3_aggln  <<<mb, 512, SMEM_BYTES>>>(We2, be2, gmsg, bmsg, mask);
    k4a_hidden<<<dim3(mb, 2), 512, SMEM_BYTES>>>(node, Wn1, bn1);
    k4b_out   <<<mb, 512, SMEM_BYTES>>>(node, Wn2, bn2, gnode, bnode, mask, out);
}